// round 10
// baseline (speedup 1.0000x reference)
#include <cuda_runtime.h>
#include <stdint.h>

// Problem constants
#define BATCH 32
#define NSEQ  512
#define CDIM  1024
#define NHEAD 16
#define HDIM  64
#define QKSCALE 0.125f

// Scratch (device globals — no allocations allowed)
__device__ float g_qh [(size_t)BATCH * NSEQ * CDIM];   // scaled q, tf32 hi
__device__ float g_ql [(size_t)BATCH * NSEQ * CDIM];   // scaled q, tf32 lo
__device__ float g_kh [(size_t)BATCH * NSEQ * CDIM];   // k tf32 hi
__device__ float g_kl [(size_t)BATCH * NSEQ * CDIM];   // k tf32 lo
__device__ float g_vr [(size_t)BATCH * NSEQ * CDIM];   // v tf32-rounded
__device__ float g_ao [(size_t)BATCH * NSEQ * CDIM];   // attention out, tf32-rounded
__device__ float g_xr [(size_t)BATCH * NSEQ * CDIM];   // x tf32-rounded
__device__ float g_wqkv[(size_t)3 * CDIM * CDIM];      // W_qkv tf32-rounded
__device__ float g_wpr [(size_t)CDIM * CDIM];          // W_proj tf32-rounded

// ---------------------------------------------------------------------------
// helpers
// ---------------------------------------------------------------------------
__device__ __forceinline__ uint32_t f2tf(float x) {
    uint32_t r;
    asm("cvt.rna.tf32.f32 %0, %1;" : "=r"(r) : "f"(x));
    return r;
}
__device__ __forceinline__ float ftf(float x) { return __uint_as_float(f2tf(x)); }

__device__ __forceinline__ void mma8(float c[4], const uint32_t a[4], const uint32_t b[2]) {
    asm volatile(
        "mma.sync.aligned.m16n8k8.row.col.f32.tf32.tf32.f32 "
        "{%0,%1,%2,%3}, {%4,%5,%6,%7}, {%8,%9}, {%0,%1,%2,%3};\n"
        : "+f"(c[0]), "+f"(c[1]), "+f"(c[2]), "+f"(c[3])
        : "r"(a[0]), "r"(a[1]), "r"(a[2]), "r"(a[3]), "r"(b[0]), "r"(b[1]));
}

__device__ __forceinline__ void cpa16(uint32_t s, const void* g) {
    asm volatile("cp.async.cg.shared.global [%0], [%1], 16;\n" :: "r"(s), "l"(g));
}
__device__ __forceinline__ void cpcommit() { asm volatile("cp.async.commit_group;\n"); }
template <int N> __device__ __forceinline__ void cpwait() {
    asm volatile("cp.async.wait_group %0;\n" :: "n"(N));
}

__device__ __forceinline__ uint32_t ldu(const float* p) {
    return *reinterpret_cast<const uint32_t*>(p);
}

// ---------------------------------------------------------------------------
// elementwise tf32 rounding pass
// ---------------------------------------------------------------------------
__global__ void round_tf32_kernel(const float4* __restrict__ src,
                                  float4* __restrict__ dst, int n4)
{
    int i = blockIdx.x * blockDim.x + threadIdx.x;
    if (i < n4) {
        float4 v = src[i];
        v.x = ftf(v.x); v.y = ftf(v.y); v.z = ftf(v.z); v.w = ftf(v.w);
        dst[i] = v;
    }
}

// ---------------------------------------------------------------------------
// GEMM:  acc[M,N] = A[M,K] * W[N,K]^T.  A/W pre-rounded to tf32 (raw-bit loads).
// Tile 128x128, BK=16, 256 threads, 8 warps (4m x 2n), cp.async double buffer.
// Epilogue mode:
//   C != null : C = acc + bias                       (proj)
//   C == null : qkv split -> qh/ql (scaled), kh/kl, vr  (QKV projection)
// ---------------------------------------------------------------------------
#define GBM 128
#define GBN 128
#define GBK 16
#define GST 20

__global__ void __launch_bounds__(256, 2)
gemm_tf32_kernel(const float* __restrict__ A, const float* __restrict__ W,
                 int K, int N,
                 float* __restrict__ C, const float* __restrict__ bias,
                 float* __restrict__ qh, float* __restrict__ ql,
                 float* __restrict__ kh, float* __restrict__ kl,
                 float* __restrict__ vr)
{
    __shared__ float As[2][GBM * GST];
    __shared__ float Bs[2][GBN * GST];

    const int tid  = threadIdx.x;
    const int lane = tid & 31;
    const int warp = tid >> 5;
    const int wm   = warp >> 1;
    const int wn   = warp & 1;

    const int m0 = blockIdx.y * GBM;
    const int n0 = blockIdx.x * GBN;

    float acc[2][8][4];
#pragma unroll
    for (int i = 0; i < 2; i++)
#pragma unroll
        for (int j = 0; j < 8; j++)
#pragma unroll
            for (int k = 0; k < 4; k++) acc[i][j][k] = 0.f;

    const int lrow = tid >> 2;
    const int lq   = (tid & 3) * 4;

    const float* Ag = A + (size_t)m0 * K;
    const float* Wg = W + (size_t)n0 * K;
    const int nk = K / GBK;

    {
        uint32_t sA = (uint32_t)__cvta_generic_to_shared(&As[0][0]);
        uint32_t sB = (uint32_t)__cvta_generic_to_shared(&Bs[0][0]);
#pragma unroll
        for (int t = 0; t < 2; t++) {
            int row = lrow + t * 64;
            cpa16(sA + (uint32_t)(row * GST + lq) * 4, Ag + (size_t)row * K + lq);
            cpa16(sB + (uint32_t)(row * GST + lq) * 4, Wg + (size_t)row * K + lq);
        }
        cpcommit();
    }

    for (int kc = 0; kc < nk; kc++) {
        if (kc + 1 < nk) {
            int buf = (kc + 1) & 1;
            int k0  = (kc + 1) * GBK;
            uint32_t sA = (uint32_t)__cvta_generic_to_shared(&As[buf][0]);
            uint32_t sB = (uint32_t)__cvta_generic_to_shared(&Bs[buf][0]);
#pragma unroll
            for (int t = 0; t < 2; t++) {
                int row = lrow + t * 64;
                cpa16(sA + (uint32_t)(row * GST + lq) * 4, Ag + (size_t)row * K + k0 + lq);
                cpa16(sB + (uint32_t)(row * GST + lq) * 4, Wg + (size_t)row * K + k0 + lq);
            }
            cpcommit();
            cpwait<1>();
        } else {
            cpwait<0>();
        }
        __syncthreads();

        const float* As_ = &As[kc & 1][0];
        const float* Bs_ = &Bs[kc & 1][0];

#pragma unroll
        for (int ks = 0; ks < 2; ks++) {
            const int kk = ks * 8;
            uint32_t af[2][4];
#pragma unroll
            for (int mi = 0; mi < 2; mi++) {
                const int r = wm * 32 + mi * 16 + (lane >> 2);
                const float* p = As_ + r * GST + kk + (lane & 3);
                af[mi][0] = ldu(p);
                af[mi][1] = ldu(p + 8 * GST);
                af[mi][2] = ldu(p + 4);
                af[mi][3] = ldu(p + 8 * GST + 4);
            }
#pragma unroll
            for (int ni = 0; ni < 8; ni++) {
                const int c = wn * 64 + ni * 8 + (lane >> 2);
                const float* p = Bs_ + c * GST + kk + (lane & 3);
                uint32_t bf[2] = { ldu(p), ldu(p + 4) };
                mma8(acc[0][ni], af[0], bf);
                mma8(acc[1][ni], af[1], bf);
            }
        }
        __syncthreads();
    }

    // ---- epilogue ----
    if (C) {
#pragma unroll
        for (int mi = 0; mi < 2; mi++) {
#pragma unroll
            for (int ni = 0; ni < 8; ni++) {
                const int r = m0 + wm * 32 + mi * 16 + (lane >> 2);
                const int c = n0 + wn * 64 + ni * 8 + 2 * (lane & 3);
                float b0 = bias ? bias[c]     : 0.f;
                float b1 = bias ? bias[c + 1] : 0.f;
                float2 v0 = make_float2(acc[mi][ni][0] + b0, acc[mi][ni][1] + b1);
                float2 v1 = make_float2(acc[mi][ni][2] + b0, acc[mi][ni][3] + b1);
                *reinterpret_cast<float2*>(C + (size_t)r * N + c)       = v0;
                *reinterpret_cast<float2*>(C + (size_t)(r + 8) * N + c) = v1;
            }
        }
    } else {
        // qkv split: n0 tile fully inside one region (256 | 1024)
        const int region = n0 >> 10;          // 0=q, 1=k, 2=v
        const int cbase  = n0 & 1023;
#pragma unroll
        for (int mi = 0; mi < 2; mi++) {
#pragma unroll
            for (int ni = 0; ni < 8; ni++) {
                const int c = cbase + wn * 64 + ni * 8 + 2 * (lane & 3);
#pragma unroll
                for (int half = 0; half < 2; half++) {
                    const size_t r = (size_t)(m0 + wm * 32 + mi * 16 + (lane >> 2) + half * 8);
                    float v0 = acc[mi][ni][2 * half + 0];
                    float v1 = acc[mi][ni][2 * half + 1];
                    size_t off = r * CDIM + c;
                    if (region == 0) {
                        float s0 = v0 * QKSCALE, s1 = v1 * QKSCALE;
                        float h0 = ftf(s0), h1 = ftf(s1);
                        *reinterpret_cast<float2*>(qh + off) = make_float2(h0, h1);
                        *reinterpret_cast<float2*>(ql + off) =
                            make_float2(ftf(s0 - h0), ftf(s1 - h1));
                    } else if (region == 1) {
                        float h0 = ftf(v0), h1 = ftf(v1);
                        *reinterpret_cast<float2*>(kh + off) = make_float2(h0, h1);
                        *reinterpret_cast<float2*>(kl + off) =
                            make_float2(ftf(v0 - h0), ftf(v1 - h1));
                    } else {
                        *reinterpret_cast<float2*>(vr + off) =
                            make_float2(ftf(v0), ftf(v1));
                    }
                }
            }
        }
    }
}

// ---------------------------------------------------------------------------
// Attention: one CTA per (b, h, 64-row q block). 256 threads, 8 warps.
// Q fragments hoisted to registers (hi/lo); K hi/lo streamed double-buffered;
// scores 64x512 in smem; zero ALU conversion in all inner loops.
// ---------------------------------------------------------------------------
#define SST 516
#define KST 68
#define STAGE_FL (2 * 64 * KST)                 // Kh + Kl per stage = 8704

#define OFF_SS 0
#define OFF_K  (64 * SST)                       // 33024
#define OFF_MS (OFF_K + 2 * STAGE_FL)           // 50432
#define OFF_RS (OFF_MS + NSEQ)                  // 50944
#define ATT_SMEM ((OFF_RS + 64) * 4)            // 204032 bytes

__global__ void __launch_bounds__(256, 1)
attn_kernel(const float* __restrict__ mask)
{
    extern __shared__ __align__(1024) float sm[];
    float* Ss = sm + OFF_SS;
    float* Kb = sm + OFF_K;
    float* Ms = sm + OFF_MS;
    float* Rs = sm + OFF_RS;

    const int tid  = threadIdx.x;
    const int lane = tid & 31;
    const int warp = tid >> 5;
    const int wm   = warp >> 1;
    const int wn   = warp & 1;

    const int qb = blockIdx.x;
    const int bh = blockIdx.y;
    const int b  = bh >> 4;
    const int h  = bh & 15;

    const float* qhg = g_qh + ((size_t)(b * NSEQ + qb * 64) * CDIM) + h * HDIM;
    const float* qlg = g_ql + ((size_t)(b * NSEQ + qb * 64) * CDIM) + h * HDIM;
    const float* khg = g_kh + ((size_t)(b * NSEQ) * CDIM) + h * HDIM;
    const float* klg = g_kl + ((size_t)(b * NSEQ) * CDIM) + h * HDIM;
    const float* vrg = g_vr + ((size_t)(b * NSEQ) * CDIM) + h * HDIM;

    // ---- phase 0: stage Q hi/lo into K buffer 0, load mask ----
    {
        uint32_t s = (uint32_t)__cvta_generic_to_shared(Kb);
#pragma unroll
        for (int t = 0; t < 4; t++) {
            int idx = tid + t * 256;
            int row = idx >> 4;
            int q4  = (idx & 15) * 4;
            cpa16(s + (uint32_t)(row * KST + q4) * 4,            qhg + (size_t)row * CDIM + q4);
            cpa16(s + (uint32_t)(64 * KST + row * KST + q4) * 4, qlg + (size_t)row * CDIM + q4);
        }
        cpcommit();
    }
    Ms[tid]       = mask[b * NSEQ + tid];
    Ms[tid + 256] = mask[b * NSEQ + tid + 256];
    cpwait<0>();
    __syncthreads();

    // ---- hoist Q fragments (all 8 k-steps, hi + lo) into registers ----
    uint32_t qah[8][4], qal[8][4];
    {
        const float* Qh_ = Kb;
        const float* Ql_ = Kb + 64 * KST;
        const int r = wm * 16 + (lane >> 2);
#pragma unroll
        for (int ks = 0; ks < 8; ks++) {
            const float* p = Qh_ + r * KST + ks * 8 + (lane & 3);
            qah[ks][0] = ldu(p);
            qah[ks][1] = ldu(p + 8 * KST);
            qah[ks][2] = ldu(p + 4);
            qah[ks][3] = ldu(p + 8 * KST + 4);
            const float* q = Ql_ + r * KST + ks * 8 + (lane & 3);
            qal[ks][0] = ldu(q);
            qal[ks][1] = ldu(q + 8 * KST);
            qal[ks][2] = ldu(q + 4);
            qal[ks][3] = ldu(q + 8 * KST + 4);
        }
    }
    __syncthreads();   // Q buffer free for K streaming

    // ---- S phase: stream K hi/lo chunks (double-buffered) ----
    auto loadK = [&](int kc) {
        uint32_t s = (uint32_t)__cvta_generic_to_shared(Kb + (kc & 1) * STAGE_FL);
#pragma unroll
        for (int t = 0; t < 4; t++) {
            int idx = tid + t * 256;
            int row = idx >> 4;
            int q4  = (idx & 15) * 4;
            size_t goff = (size_t)(kc * 64 + row) * CDIM + q4;
            cpa16(s + (uint32_t)(row * KST + q4) * 4,            khg + goff);
            cpa16(s + (uint32_t)(64 * KST + row * KST + q4) * 4, klg + goff);
        }
        cpcommit();
    };

    loadK(0);

    for (int kc = 0; kc < 8; kc++) {
        if (kc + 1 < 8) { loadK(kc + 1); cpwait<1>(); }
        else            { cpwait<0>(); }
        __syncthreads();

        const float* Kh_ = Kb + (kc & 1) * STAGE_FL;
        const float* Kl_ = Kh_ + 64 * KST;

        float sacc[4][4];
#pragma unroll
        for (int i = 0; i < 4; i++)
#pragma unroll
            for (int j = 0; j < 4; j++) sacc[i][j] = 0.f;

#pragma unroll
        for (int ks = 0; ks < 8; ks++) {
            const int kk = ks * 8;
#pragma unroll
            for (int ni = 0; ni < 4; ni++) {
                const int c = wn * 32 + ni * 8 + (lane >> 2);
                const float* ph = Kh_ + c * KST + kk + (lane & 3);
                const float* pl = Kl_ + c * KST + kk + (lane & 3);
                uint32_t bh2[2] = { ldu(ph), ldu(ph + 4) };
                uint32_t bl2[2] = { ldu(pl), ldu(pl + 4) };
                mma8(sacc[ni], qah[ks], bh2);
                mma8(sacc[ni], qal[ks], bh2);
                mma8(sacc[ni], qah[ks], bl2);
            }
        }

#pragma unroll
        for (int ni = 0; ni < 4; ni++) {
            const int r  = wm * 16 + (lane >> 2);
            const int cc = kc * 64 + wn * 32 + ni * 8 + 2 * (lane & 3);
            Ss[r * SST + cc]           = sacc[ni][0] + Ms[cc];
            Ss[r * SST + cc + 1]       = sacc[ni][1] + Ms[cc + 1];
            Ss[(r + 8) * SST + cc]     = sacc[ni][2] + Ms[cc];
            Ss[(r + 8) * SST + cc + 1] = sacc[ni][3] + Ms[cc + 1];
        }
        __syncthreads();
    }

    // ---- softmax (each warp owns 8 rows); store tf32-rounded exp ----
#pragma unroll 1
    for (int rr = 0; rr < 8; rr++) {
        const int r = warp * 8 + rr;
        float* srow = Ss + r * SST;
        float mx = -1e30f;
#pragma unroll
        for (int j = 0; j < 16; j++) mx = fmaxf(mx, srow[lane + j * 32]);
#pragma unroll
        for (int o = 16; o > 0; o >>= 1) mx = fmaxf(mx, __shfl_xor_sync(0xffffffffu, mx, o));
        float sum = 0.f;
#pragma unroll
        for (int j = 0; j < 16; j++) {
            float e = ftf(__expf(srow[lane + j * 32] - mx));
            srow[lane + j * 32] = e;
            sum += e;
        }
#pragma unroll
        for (int o = 16; o > 0; o >>= 1) sum += __shfl_xor_sync(0xffffffffu, sum, o);
        if (lane == 0) Rs[r] = 1.f / sum;
    }
    __syncthreads();

    // ---- PV phase ----
    float oacc[4][4];
#pragma unroll
    for (int i = 0; i < 4; i++)
#pragma unroll
        for (int j = 0; j < 4; j++) oacc[i][j] = 0.f;

    float* Vs = Kb;  // reuse, transposed [hd][VST=KST]
    for (int vc = 0; vc < 8; vc++) {
#pragma unroll
        for (int t = 0; t < 4; t++) {
            int idx = tid + t * 256;
            int key = idx & 63;
            int qq  = (idx >> 6) * 4;
            float4 v = *reinterpret_cast<const float4*>(
                vrg + (size_t)(vc * 64 + key) * CDIM + qq);
            Vs[(qq + 0) * KST + key] = v.x;
            Vs[(qq + 1) * KST + key] = v.y;
            Vs[(qq + 2) * KST + key] = v.z;
            Vs[(qq + 3) * KST + key] = v.w;
        }
        __syncthreads();

#pragma unroll
        for (int ks = 0; ks < 8; ks++) {
            uint32_t af[4];
            {
                const int r = wm * 16 + (lane >> 2);
                const float* p = Ss + r * SST + vc * 64 + ks * 8 + (lane & 3);
                af[0] = ldu(p);
                af[1] = ldu(p + 8 * SST);
                af[2] = ldu(p + 4);
                af[3] = ldu(p + 8 * SST + 4);
            }
#pragma unroll
            for (int ni = 0; ni < 4; ni++) {
                const int n = wn * 32 + ni * 8 + (lane >> 2);
                const float* p = Vs + n * KST + ks * 8 + (lane & 3);
                uint32_t bf[2] = { ldu(p), ldu(p + 4) };
                mma8(oacc[ni], af, bf);
            }
        }
        __syncthreads();
    }

    // ---- epilogue: normalize + tf32-round (feeds proj GEMM raw loads) ----
    float* aob = g_ao + ((size_t)(b * NSEQ + qb * 64) * CDIM) + h * HDIM;
    const int r = wm * 16 + (lane >> 2);
    const float inv0 = Rs[r];
    const float inv1 = Rs[r + 8];
#pragma unroll
    for (int ni = 0; ni < 4; ni++) {
        const int c = wn * 32 + ni * 8 + 2 * (lane & 3);
        float2 v0 = make_float2(ftf(oacc[ni][0] * inv0), ftf(oacc[ni][1] * inv0));
        float2 v1 = make_float2(ftf(oacc[ni][2] * inv1), ftf(oacc[ni][3] * inv1));
        *reinterpret_cast<float2*>(aob + (size_t)r * CDIM + c)       = v0;
        *reinterpret_cast<float2*>(aob + (size_t)(r + 8) * CDIM + c) = v1;
    }
}

// ---------------------------------------------------------------------------
// launcher
// ---------------------------------------------------------------------------
extern "C" void kernel_launch(void* const* d_in, const int* in_sizes, int n_in,
                              void* d_out, int out_size)
{
    (void)in_sizes; (void)n_in; (void)out_size;

    const float* x     = (const float*)d_in[0];
    const float* mask  = (const float*)d_in[1];
    const float* Wqkv  = (const float*)d_in[2];
    const float* Wproj = (const float*)d_in[3];
    const float* bproj = (const float*)d_in[4];
    float* out = (float*)d_out;

    float *qh, *ql, *kh, *kl, *vr, *ao, *xr, *wqkv, *wpr;
    cudaGetSymbolAddress((void**)&qh,   g_qh);
    cudaGetSymbolAddress((void**)&ql,   g_ql);
    cudaGetSymbolAddress((void**)&kh,   g_kh);
    cudaGetSymbolAddress((void**)&kl,   g_kl);
    cudaGetSymbolAddress((void**)&vr,   g_vr);
    cudaGetSymbolAddress((void**)&ao,   g_ao);
    cudaGetSymbolAddress((void**)&xr,   g_xr);
    cudaGetSymbolAddress((void**)&wqkv, g_wqkv);
    cudaGetSymbolAddress((void**)&wpr,  g_wpr);

    cudaFuncSetAttribute(attn_kernel, cudaFuncAttributeMaxDynamicSharedMemorySize, ATT_SMEM);

    // 0) pre-round GEMM inputs to tf32 (enables raw-bit fragment loads)
    {
        int n4x = BATCH * NSEQ * CDIM / 4;
        int n4q = 3 * CDIM * CDIM / 4;
        int n4p = CDIM * CDIM / 4;
        round_tf32_kernel<<<(n4x + 255) / 256, 256>>>((const float4*)x,     (float4*)xr,   n4x);
        round_tf32_kernel<<<(n4q + 255) / 256, 256>>>((const float4*)Wqkv,  (float4*)wqkv, n4q);
        round_tf32_kernel<<<(n4p + 255) / 256, 256>>>((const float4*)Wproj, (float4*)wpr,  n4p);
    }

    // 1) QKV projection + fused hi/lo split epilogue
    gemm_tf32_kernel<<<dim3(3 * CDIM / GBN, (BATCH * NSEQ) / GBM), 256>>>(
        xr, wqkv, CDIM, 3 * CDIM, nullptr, nullptr, qh, ql, kh, kl, vr);

    // 2) fused attention -> g_ao (tf32-rounded)
    attn_kernel<<<dim3(NSEQ / 64, BATCH * NHEAD), 256, ATT_SMEM>>>(mask);

    // 3) output projection (+bias)
    gemm_tf32_kernel<<<dim3(CDIM / GBN, (BATCH * NSEQ) / GBM), 256>>>(
        ao, wpr, CDIM, CDIM, out, bproj, nullptr, nullptr, nullptr, nullptr, nullptr);
}